// round 17
// baseline (speedup 1.0000x reference)
#include <cuda_runtime.h>

#define BB   2048
#define CC   128
#define II   16
#define EE   10
#define NT   816     // symmetric triples i<=j<=l
#define NP   136     // symmetric pairs  i<=j
#define NS   16      // singles
#define NTOT 968     // NT+NP+NS
#define K30  23
#define K31  33
#define K20  4
#define K21  5

// ---------------- device scratch (no allocations allowed) ----------------
__device__ float g_U3sym0[NT * K30];
__device__ float g_U3sym1[3 * NT * K31];
__device__ float g_U2sym0[NP * K20];
__device__ float g_U2sym1[3 * NP * K21];
// S planes: [e][c][m][t]
__device__ float g_S[(size_t)EE * CC * 4 * NTOT];   // ~19.8MB
__device__ int   g_order[BB];
__device__ int   g_offsets[EE + 1];

// ---------------- f32x2 packed helpers ----------------
__device__ __forceinline__ unsigned long long pk2(float a, float b) {
    unsigned long long r;
    asm("mov.b64 %0, {%1, %2};" : "=l"(r) : "f"(a), "f"(b));
    return r;
}
__device__ __forceinline__ unsigned long long dup2(float a) {
    unsigned long long r;
    asm("mov.b64 %0, {%1, %1};" : "=l"(r) : "f"(a));
    return r;
}
__device__ __forceinline__ void unpk2(unsigned long long v, float& lo, float& hi) {
    asm("mov.b64 {%0, %1}, %2;" : "=f"(lo), "=f"(hi) : "l"(v));
}
#define MUL2(d, a, b) asm("mul.rn.f32x2 %0, %1, %2;" : "=l"(d) : "l"(a), "l"(b))
#define FMA2(d, a, b) asm("fma.rn.f32x2 %0, %1, %2, %0;" : "+l"(d) : "l"(a), "l"(b))
#define ADD2(d, a)    asm("add.rn.f32x2 %0, %0, %1;"     : "+l"(d) : "l"(a))

// ---------------- compile-time slot offsets ----------------
__host__ __device__ constexpr int triN(int m) { return m * (m + 1) / 2; }
__host__ __device__ constexpr int c3_before(int i) {
    int s = 0;
    for (int a = 0; a < i; a++) s += triN(II - a);
    return s;
}
__host__ __device__ constexpr int c2_before(int i) {
    int s = 0;
    for (int a = 0; a < i; a++) s += (II - a);
    return s;
}

// ---------------- index helpers ----------------
__device__ __forceinline__ void unrank3(int t, int& a, int& b, int& c) {
    int n = 0;
    for (int i = 0; i < II; i++)
        for (int j = i; j < II; j++) {
            int len = II - j;
            if (t < n + len) { a = i; b = j; c = j + (t - n); return; }
            n += len;
        }
    a = b = c = 0;
}
__device__ __forceinline__ void unrank2(int t, int& a, int& b) {
    int n = 0;
    for (int i = 0; i < II; i++)
        for (int j = i; j < II; j++) {
            if (t == n) { a = i; b = j; return; }
            n++;
        }
    a = b = 0;
}

// ---------------- no-op (profiling slot alignment) ----------------
__global__ void k_nop() {}

// ---------------- fused prep: sym3 + sym2 + element bucketing ----------------
__global__ void __launch_bounds__(256) k_prep(
        const float* __restrict__ U3_0, const float* __restrict__ U3_1,
        const float* __restrict__ U2_0, const float* __restrict__ U2_1,
        const float* __restrict__ y) {
    int bid = blockIdx.x;
    int tid = threadIdx.x;

    if (bid < NT) {
        int t  = bid;
        int ms = tid >> 6;
        int k  = tid & 63;
        int K  = (ms == 0) ? K30 : K31;
        if (k >= K) return;
        int a, b, c;
        unrank3(t, a, b, c);
        int P[6][3] = {{a,b,c},{a,c,b},{b,a,c},{b,c,a},{c,a,b},{c,b,a}};
        float s = 0.f;
        for (int p = 0; p < 6; p++) {
            bool dup = false;
            for (int q = 0; q < p; q++)
                if (P[q][0]==P[p][0] && P[q][1]==P[p][1] && P[q][2]==P[p][2]) { dup = true; break; }
            if (dup) continue;
            int i = P[p][0], j = P[p][1], l = P[p][2];
            if (ms == 0) s += U3_0[((i*II + j)*II + l)*K30 + k];
            else         s += U3_1[((((ms-1)*II + i)*II + j)*II + l)*K31 + k];
        }
        if (ms == 0) g_U3sym0[t*K30 + k] = s;
        else         g_U3sym1[((ms-1)*NT + t)*K31 + k] = s;
    } else if (bid < NT + 34) {
        int p  = (bid - NT) * 4 + (tid >> 6);
        if (p >= NP) return;
        int ms = (tid >> 4) & 3;
        int k  = tid & 15;
        int K  = (ms == 0) ? K20 : K21;
        if (k >= K) return;
        int a, b;
        unrank2(p, a, b);
        if (ms == 0) {
            float s = U2_0[(a*II + b)*K20 + k];
            if (a != b) s += U2_0[(b*II + a)*K20 + k];
            g_U2sym0[p*K20 + k] = s;
        } else {
            int mm = ms - 1;
            float s = U2_1[((mm*II + a)*II + b)*K21 + k];
            if (a != b) s += U2_1[((mm*II + b)*II + a)*K21 + k];
            g_U2sym1[(mm*NP + p)*K21 + k] = s;
        }
    } else {
        // ---- bucketing: one block, 256 threads x 8 nodes ----
        __shared__ int cnt[EE], cur[EE], offs[EE];
        if (tid < EE) cnt[tid] = 0;
        __syncthreads();
        int myE[8];
        #pragma unroll
        for (int q = 0; q < 8; q++) {
            int b = tid * 8 + q;
            const float* yr = y + (size_t)b * EE;
            int e = 0; float best = yr[0];
            #pragma unroll
            for (int r = 1; r < EE; r++) { float v = yr[r]; if (v > best) { best = v; e = r; } }
            myE[q] = e;
            atomicAdd(&cnt[e], 1);
        }
        __syncthreads();
        if (tid == 0) {
            int s = 0;
            for (int e = 0; e < EE; e++) { offs[e] = s; g_offsets[e] = s; s += cnt[e]; }
            g_offsets[EE] = s;
        }
        if (tid < EE) cur[tid] = 0;
        __syncthreads();
        #pragma unroll
        for (int q = 0; q < 8; q++) {
            int b = tid * 8 + q;
            int e = myE[q];
            int pos = atomicAdd(&cur[e], 1);
            g_order[offs[e] + pos] = b;
        }
    }
}

// ---------------- build S planes (f32x2 packed over channel pairs) ----------------
__global__ void __launch_bounds__(256) k_S(
        const float* __restrict__ W3_0, const float* __restrict__ W2_0,
        const float* __restrict__ W1_0, const float* __restrict__ W3_1,
        const float* __restrict__ W2_1, const float* __restrict__ W1_1,
        const float* __restrict__ U1_0, const float* __restrict__ U1_1) {
    __shared__ unsigned long long Wp30[K30][16];
    __shared__ unsigned long long Wp31[K31][16];
    __shared__ unsigned long long Wp20[K20][16];
    __shared__ unsigned long long Wp21[K21][16];
    __shared__ float Ws10[32], Ws11[32];

    int tid = threadIdx.x;
    int c0  = blockIdx.x * 32;
    int e   = blockIdx.z;
    int t   = blockIdx.y * 256 + tid;

    for (int idx = tid; idx < K30*16; idx += 256) {
        int k = idx / 16, cp = idx % 16;
        const float* w = W3_0 + ((size_t)e*K30 + k)*CC + c0 + 2*cp;
        Wp30[k][cp] = pk2(w[0], w[1]);
    }
    for (int idx = tid; idx < K31*16; idx += 256) {
        int k = idx / 16, cp = idx % 16;
        const float* w = W3_1 + ((size_t)e*K31 + k)*CC + c0 + 2*cp;
        Wp31[k][cp] = pk2(w[0], w[1]);
    }
    for (int idx = tid; idx < K20*16; idx += 256) {
        int k = idx / 16, cp = idx % 16;
        const float* w = W2_0 + ((size_t)e*K20 + k)*CC + c0 + 2*cp;
        Wp20[k][cp] = pk2(w[0], w[1]);
    }
    for (int idx = tid; idx < K21*16; idx += 256) {
        int k = idx / 16, cp = idx % 16;
        const float* w = W2_1 + ((size_t)e*K21 + k)*CC + c0 + 2*cp;
        Wp21[k][cp] = pk2(w[0], w[1]);
    }
    if (tid < 32) {
        Ws10[tid] = W1_0[(size_t)e*CC + c0 + tid];
        Ws11[tid] = W1_1[(size_t)e*CC + c0 + tid];
    }
    __syncthreads();
    if (t >= NTOT) return;

    float* plane = g_S + ((size_t)e*CC + c0) * 4 * NTOT;   // + (c*4+m)*NTOT + t

    if (t < NT) {
        {   // m = 0
            unsigned long long acc[16];
            #pragma unroll
            for (int cp = 0; cp < 16; cp++) acc[cp] = 0ull;
            const float* u = &g_U3sym0[t*K30];
            for (int k = 0; k < K30; k++) {
                unsigned long long ud = dup2(u[k]);
                #pragma unroll
                for (int cp = 0; cp < 16; cp++) FMA2(acc[cp], ud, Wp30[k][cp]);
            }
            #pragma unroll
            for (int cp = 0; cp < 16; cp++) {
                float lo, hi; unpk2(acc[cp], lo, hi);
                plane[(size_t)((2*cp  )*4 + 0)*NTOT + t] = lo;
                plane[(size_t)((2*cp+1)*4 + 0)*NTOT + t] = hi;
            }
        }
        for (int m = 1; m < 4; m++) {
            unsigned long long acc[16];
            #pragma unroll
            for (int cp = 0; cp < 16; cp++) acc[cp] = 0ull;
            const float* u = &g_U3sym1[((m-1)*NT + t)*K31];
            for (int k = 0; k < K31; k++) {
                unsigned long long ud = dup2(u[k]);
                #pragma unroll
                for (int cp = 0; cp < 16; cp++) FMA2(acc[cp], ud, Wp31[k][cp]);
            }
            #pragma unroll
            for (int cp = 0; cp < 16; cp++) {
                float lo, hi; unpk2(acc[cp], lo, hi);
                plane[(size_t)((2*cp  )*4 + m)*NTOT + t] = lo;
                plane[(size_t)((2*cp+1)*4 + m)*NTOT + t] = hi;
            }
        }
    } else if (t < NT + NP) {
        int p = t - NT;
        {   unsigned long long acc[16];
            #pragma unroll
            for (int cp = 0; cp < 16; cp++) acc[cp] = 0ull;
            const float* u = &g_U2sym0[p*K20];
            for (int k = 0; k < K20; k++) {
                unsigned long long ud = dup2(u[k]);
                #pragma unroll
                for (int cp = 0; cp < 16; cp++) FMA2(acc[cp], ud, Wp20[k][cp]);
            }
            #pragma unroll
            for (int cp = 0; cp < 16; cp++) {
                float lo, hi; unpk2(acc[cp], lo, hi);
                plane[(size_t)((2*cp  )*4 + 0)*NTOT + t] = lo;
                plane[(size_t)((2*cp+1)*4 + 0)*NTOT + t] = hi;
            }
        }
        for (int m = 1; m < 4; m++) {
            unsigned long long acc[16];
            #pragma unroll
            for (int cp = 0; cp < 16; cp++) acc[cp] = 0ull;
            const float* u = &g_U2sym1[((m-1)*NP + p)*K21];
            for (int k = 0; k < K21; k++) {
                unsigned long long ud = dup2(u[k]);
                #pragma unroll
                for (int cp = 0; cp < 16; cp++) FMA2(acc[cp], ud, Wp21[k][cp]);
            }
            #pragma unroll
            for (int cp = 0; cp < 16; cp++) {
                float lo, hi; unpk2(acc[cp], lo, hi);
                plane[(size_t)((2*cp  )*4 + m)*NTOT + t] = lo;
                plane[(size_t)((2*cp+1)*4 + m)*NTOT + t] = hi;
            }
        }
    } else {
        int i = t - NT - NP;
        float u0 = U1_0[i];
        float u1 = U1_1[0*II + i], u2 = U1_1[1*II + i], u3 = U1_1[2*II + i];
        for (int c = 0; c < 32; c++) {
            plane[(size_t)(c*4 + 0)*NTOT + t] = u0 * Ws10[c];
            plane[(size_t)(c*4 + 1)*NTOT + t] = u1 * Ws11[c];
            plane[(size_t)(c*4 + 2)*NTOT + t] = u2 * Ws11[c];
            plane[(size_t)(c*4 + 3)*NTOT + t] = u3 * Ws11[c];
        }
    }
}

// ---------------- partial walk over i-rows [IB, IE) ----------------
template<int IB, int IE>
__device__ __forceinline__ void walk_rows(
        const ulonglong2* __restrict__ Sd,
        const unsigned long long* __restrict__ xd0,
        const unsigned long long* __restrict__ xd1,
        const unsigned long long* __restrict__ xd2,
        const unsigned long long* __restrict__ xd3,
        unsigned long long& aL0, unsigned long long& aH0,
        unsigned long long& aL1, unsigned long long& aH1,
        unsigned long long& aL2, unsigned long long& aH2,
        unsigned long long& aL3, unsigned long long& aH3) {
    int t3 = c3_before(IB);        // cubic slot counter
    int tq = NT + c2_before(IB);   // quadratic slot counter
    #pragma unroll
    for (int i = IB; i < IE; i++) {
        #pragma unroll
        for (int j = i; j < II; j++) {
            unsigned long long p0, p1, p2, p3;
            MUL2(p0, xd0[i], xd0[j]);
            MUL2(p1, xd1[i], xd1[j]);
            MUL2(p2, xd2[i], xd2[j]);
            MUL2(p3, xd3[i], xd3[j]);
            ulonglong2 qS = Sd[tq];
            tq++;
            unsigned long long iL0=qS.x, iH0=qS.y, iL1=qS.x, iH1=qS.y;
            unsigned long long iL2=qS.x, iH2=qS.y, iL3=qS.x, iH3=qS.y;
            ulonglong2 cur = Sd[t3];
            #pragma unroll
            for (int l = j; l < II; l++) {
                ulonglong2 nxt;
                if (l < II - 1) nxt = Sd[t3 + 1];
                FMA2(iL0, xd0[l], cur.x);
                FMA2(iH0, xd0[l], cur.y);
                FMA2(iL1, xd1[l], cur.x);
                FMA2(iH1, xd1[l], cur.y);
                FMA2(iL2, xd2[l], cur.x);
                FMA2(iH2, xd2[l], cur.y);
                FMA2(iL3, xd3[l], cur.x);
                FMA2(iH3, xd3[l], cur.y);
                if (l < II - 1) cur = nxt;
                t3++;
            }
            FMA2(aL0, p0, iL0);
            FMA2(aH0, p0, iH0);
            FMA2(aL1, p1, iL1);
            FMA2(aH1, p1, iH1);
            FMA2(aL2, p2, iL2);
            FMA2(aH2, p2, iH2);
            FMA2(aL3, p3, iL3);
            FMA2(aH3, p3, iH3);
        }
        // linear slot i
        {
            ulonglong2 lS = Sd[NT + NP + i];
            FMA2(aL0, xd0[i], lS.x);
            FMA2(aH0, xd0[i], lS.y);
            FMA2(aL1, xd1[i], lS.x);
            FMA2(aH1, xd1[i], lS.y);
            FMA2(aL2, xd2[i], lS.x);
            FMA2(aH2, xd2[i], lS.y);
            FMA2(aL3, xd3[i], lS.x);
            FMA2(aH3, xd3[i], lS.y);
        }
    }
}

// ---------------- main contraction: grid (c, e, node-half), 64 threads.
// Both warps cover the SAME 128 nodes (4/lane x 32 lanes); warp0 sweeps
// i-rows {0..2, 11..15}, warp1 rows {3..10} (fp-balanced 50/50); partials
// combined via one f32x2 add. Walks are T/2 => finer wave quantization. ----
__global__ void __launch_bounds__(64, 6) k_main(const float* __restrict__ x,
                                                float* __restrict__ out) {
    __shared__ ulonglong2 Sd[NTOT];              // 15.5KB
    __shared__ unsigned long long Red[32][8];    // warp1 partials, 2KB
    int c    = blockIdx.x;
    int e    = blockIdx.y;
    int h    = blockIdx.z;          // node-half within bucket
    int tid  = threadIdx.x;
    int lane = tid & 31;
    int warp = tid >> 5;

    const float* P = g_S + ((size_t)e*CC + c) * 4 * NTOT;
    for (int t = tid; t < NTOT; t += 64) {
        Sd[t] = make_ulonglong2(pk2(P[0*NTOT + t], P[1*NTOT + t]),
                                pk2(P[2*NTOT + t], P[3*NTOT + t]));
    }
    __syncthreads();

    int off = g_offsets[e];
    int n   = g_offsets[e+1] - off;

    int i0 = h * 128 + 4 * lane;
    int nd[4];
    #pragma unroll
    for (int q = 0; q < 4; q++) nd[q] = (i0 + q < n) ? g_order[off + i0 + q] : -1;

    // duplicated per-node x values: xd[q][i] = (x_i, x_i) for node q
    unsigned long long xd0[II], xd1[II], xd2[II], xd3[II];
    {
        #pragma unroll
        for (int q = 0; q < 4; q++) {
            const float4* p = (nd[q] >= 0)
                ? reinterpret_cast<const float4*>(x + ((size_t)nd[q]*CC + c)*II) : nullptr;
            unsigned long long* xq = (q==0)?xd0:(q==1)?xd1:(q==2)?xd2:xd3;
            #pragma unroll
            for (int r = 0; r < 4; r++) {
                float4 v = (nd[q] >= 0) ? p[r] : make_float4(0.f,0.f,0.f,0.f);
                xq[r*4+0] = dup2(v.x); xq[r*4+1] = dup2(v.y);
                xq[r*4+2] = dup2(v.z); xq[r*4+3] = dup2(v.w);
            }
        }
    }

    unsigned long long aL0=0ull,aH0=0ull, aL1=0ull,aH1=0ull,
                       aL2=0ull,aH2=0ull, aL3=0ull,aH3=0ull;

    if (warp == 0) {
        walk_rows<0, 3>(Sd, xd0, xd1, xd2, xd3, aL0,aH0,aL1,aH1,aL2,aH2,aL3,aH3);
        walk_rows<11,16>(Sd, xd0, xd1, xd2, xd3, aL0,aH0,aL1,aH1,aL2,aH2,aL3,aH3);
    } else {
        walk_rows<3,11>(Sd, xd0, xd1, xd2, xd3, aL0,aH0,aL1,aH1,aL2,aH2,aL3,aH3);
        Red[lane][0] = aL0; Red[lane][1] = aH0;
        Red[lane][2] = aL1; Red[lane][3] = aH1;
        Red[lane][4] = aL2; Red[lane][5] = aH2;
        Red[lane][6] = aL3; Red[lane][7] = aH3;
    }
    __syncthreads();

    if (warp == 0) {
        ADD2(aL0, Red[lane][0]); ADD2(aH0, Red[lane][1]);
        ADD2(aL1, Red[lane][2]); ADD2(aH1, Red[lane][3]);
        ADD2(aL2, Red[lane][4]); ADD2(aH2, Red[lane][5]);
        ADD2(aL3, Red[lane][6]); ADD2(aH3, Red[lane][7]);

        float r[4][4];
        unpk2(aL0, r[0][0], r[0][1]);  unpk2(aH0, r[0][2], r[0][3]);
        unpk2(aL1, r[1][0], r[1][1]);  unpk2(aH1, r[1][2], r[1][3]);
        unpk2(aL2, r[2][0], r[2][1]);  unpk2(aH2, r[2][2], r[2][3]);
        unpk2(aL3, r[3][0], r[3][1]);  unpk2(aH3, r[3][2], r[3][3]);

        #pragma unroll
        for (int q = 0; q < 4; q++) {
            if (nd[q] >= 0) {
                float* o = out + (size_t)nd[q] * (4*CC);
                o[c]            = r[q][0];
                o[CC + c*3 + 0] = r[q][1];
                o[CC + c*3 + 1] = r[q][2];
                o[CC + c*3 + 2] = r[q][3];
            }
        }
    }
}

// ---------------- launch ----------------
extern "C" void kernel_launch(void* const* d_in, const int* in_sizes, int n_in,
                              void* d_out, int out_size) {
    const float* x    = (const float*)d_in[0];
    const float* y    = (const float*)d_in[1];
    const float* U3_0 = (const float*)d_in[2];
    const float* U2_0 = (const float*)d_in[3];
    const float* U1_0 = (const float*)d_in[4];
    const float* W3_0 = (const float*)d_in[5];
    const float* W2_0 = (const float*)d_in[6];
    const float* W1_0 = (const float*)d_in[7];
    const float* U3_1 = (const float*)d_in[8];
    const float* U2_1 = (const float*)d_in[9];
    const float* U1_1 = (const float*)d_in[10];
    const float* W3_1 = (const float*)d_in[11];
    const float* W2_1 = (const float*)d_in[12];
    const float* W1_1 = (const float*)d_in[13];
    float* out = (float*)d_out;

    k_nop<<<1, 32>>>();   // keeps k_main in the ncu capture slot (#4)
    k_prep<<<NT + 34 + 1, 256>>>(U3_0, U3_1, U2_0, U2_1, y);
    k_S<<<dim3(4, 4, EE), 256>>>(W3_0, W2_0, W1_0, W3_1, W2_1, W1_1, U1_0, U1_1);
    k_main<<<dim3(CC, EE, 2), 64>>>(x, out);
}